// round 6
// baseline (speedup 1.0000x reference)
#include <cuda_runtime.h>

#define N_NODES 50000
#define N_EDGES 800000
#define IN_F    128
#define OUT_F   64
#define NEG_SLOPE 0.2f
#define MAXDEG  128   // deg ~ Poisson(16); max over 50K nodes ~50. Huge margin.

// ---------------- scratch (static device globals; no allocs) ----------------
__device__ float g_h[(size_t)N_NODES * OUT_F];          // 12.8 MB
__device__ float g_asrc[N_NODES];
__device__ float g_adst[N_NODES];
__device__ float g_denom[N_NODES];
__device__ int   g_count[N_NODES];
__device__ int   g_slots[(size_t)N_NODES * MAXDEG];     // src ids, 25.6 MB
__device__ float g_pvals[(size_t)N_NODES * MAXDEG];     // p per edge, 25.6 MB
__device__ int   g_is64;

// ---------------- K0: zero counts+denom, detect dtype (block 0) -------------
// int64 LE: every odd 32-bit word is 0 (ids in [0,50000)). int32: odd words
// are node ids; 1024 consecutive zeros is ~impossible.
__global__ void k_detz(const unsigned int* __restrict__ w) {
    int t = blockIdx.x * blockDim.x + threadIdx.x;
    if (t < N_NODES) { g_count[t] = 0; g_denom[t] = 0.0f; }
    if (blockIdx.x == 0) {
        int nz = 0;
        #pragma unroll
        for (int j = 0; j < 4; j++)
            nz |= (w[2 * (threadIdx.x + 256 * j) + 1] != 0u) ? 1 : 0;
        int any = __syncthreads_or(nz);
        if (threadIdx.x == 0) g_is64 = any ? 0 : 1;
    }
}

// ---------------- K1: h = x @ W, packed f32x2 FMA, 2 cols/thread ------------
// Per k: 2 LDS.128 (x row-pairs) + 1 LDS.64 (w pair) -> 8 FFMA2.
__global__ __launch_bounds__(128) void k_gemm(const float* __restrict__ x,
                                              const float* __restrict__ W,
                                              const float* __restrict__ att_src,
                                              const float* __restrict__ att_dst) {
    __shared__ __align__(16) float xs_t[IN_F][32];   // 16 KB, k-major x tile
    __shared__ __align__(16) float Ws[IN_F][OUT_F];  // 32 KB
    float (*hs)[OUT_F] = (float (*)[OUT_F]) & xs_t[0][0];  // alias after sync

    const int tx = threadIdx.x;
    const int lane = tx & 31;
    const int warp = tx >> 5;
    const int rbase = blockIdx.x * 32;

    const float as0 = att_src[lane], as1 = att_src[32 + lane];
    const float ad0 = att_dst[lane], ad1 = att_dst[32 + lane];

    {   // load W: 2048 float4 / 128 threads
        const float4* W4 = (const float4*)W;
        float4* Ws4 = (float4*)&Ws[0][0];
        #pragma unroll
        for (int i = 0; i < 16; i++) Ws4[tx + 128 * i] = W4[tx + 128 * i];
    }
    {   // load x tile transposed
        const int row = tx & 31;
        const int kq = tx >> 5;
        const int grow = rbase + row;
        const float4* x4 = (const float4*)x;
        #pragma unroll
        for (int j = 0; j < 8; j++) {
            int k4 = kq + 4 * j;
            float4 v = (grow < N_NODES) ? x4[(size_t)grow * (IN_F / 4) + k4]
                                        : make_float4(0.f, 0.f, 0.f, 0.f);
            xs_t[4 * k4 + 0][row] = v.x;
            xs_t[4 * k4 + 1][row] = v.y;
            xs_t[4 * k4 + 2][row] = v.z;
            xs_t[4 * k4 + 3][row] = v.w;
        }
    }
    __syncthreads();

    const int cp = tx & 31;   // cols 2cp, 2cp+1
    const int rg = tx >> 5;   // rows rg*8..rg*8+7 (4 packed pairs)
    unsigned long long acc[4][2];
    #pragma unroll
    for (int j = 0; j < 4; j++) { acc[j][0] = 0ull; acc[j][1] = 0ull; }

    #pragma unroll 4
    for (int k = 0; k < IN_F; k++) {
        float2 wv = *(const float2*)&Ws[k][2 * cp];
        unsigned long long w20, w21;
        asm("mov.b64 %0, {%1, %1};" : "=l"(w20) : "r"(__float_as_uint(wv.x)));
        asm("mov.b64 %0, {%1, %1};" : "=l"(w21) : "r"(__float_as_uint(wv.y)));
        // two 16B broadcast loads cover all 4 row-pairs
        ulonglong2 xa = *(const ulonglong2*)&xs_t[k][rg * 8];
        ulonglong2 xb = *(const ulonglong2*)&xs_t[k][rg * 8 + 4];
        unsigned long long xp[4] = {xa.x, xa.y, xb.x, xb.y};
        #pragma unroll
        for (int j = 0; j < 4; j++) {
            asm("fma.rn.f32x2 %0, %1, %2, %3;"
                : "=l"(acc[j][0]) : "l"(xp[j]), "l"(w20), "l"(acc[j][0]));
            asm("fma.rn.f32x2 %0, %1, %2, %3;"
                : "=l"(acc[j][1]) : "l"(xp[j]), "l"(w21), "l"(acc[j][1]));
        }
    }
    __syncthreads();

    #pragma unroll
    for (int j = 0; j < 4; j++) {
        int r0 = rg * 8 + 2 * j;
        hs[r0][2 * cp]         = __uint_as_float((unsigned)acc[j][0]);
        hs[r0 + 1][2 * cp]     = __uint_as_float((unsigned)(acc[j][0] >> 32));
        hs[r0][2 * cp + 1]     = __uint_as_float((unsigned)acc[j][1]);
        hs[r0 + 1][2 * cp + 1] = __uint_as_float((unsigned)(acc[j][1] >> 32));
    }
    __syncthreads();

    {   // coalesced copy hs -> g_h
        const float4* hs4 = (const float4*)&hs[0][0];
        float4* gh4 = (float4*)g_h;
        #pragma unroll
        for (int i = 0; i < 4; i++) {
            int idx = tx + 128 * i;
            int r = idx >> 4;
            if (rbase + r < N_NODES)
                gh4[(size_t)(rbase + r) * 16 + (idx & 15)] = hs4[idx];
        }
    }

    // fused attn: warp w reduces rows 8w..8w+7
    #pragma unroll
    for (int rr = 0; rr < 8; rr++) {
        int r = warp * 8 + rr;
        float h0 = hs[r][lane], h1 = hs[r][32 + lane];
        float s = h0 * as0 + h1 * as1;
        float d = h0 * ad0 + h1 * ad1;
        #pragma unroll
        for (int o = 16; o; o >>= 1) {
            s += __shfl_xor_sync(0xffffffffu, s, o);
            d += __shfl_xor_sync(0xffffffffu, d, o);
        }
        int gr = rbase + r;
        if (lane == 0 && gr < N_NODES) { g_asrc[gr] = s; g_adst[gr] = d; }
    }
}

// ---------------- K2: bucket + softmax numerator, 4 edges/thread -----------
__global__ __launch_bounds__(256) void k_fill(const void* __restrict__ ei) {
    int base = (blockIdx.x * blockDim.x + threadIdx.x) * 4;
    const int* w = (const int*)ei;
    const bool is64 = (g_is64 != 0);

    int s[4], d[4], slot[4];
    float av[4], bv[4];
    #pragma unroll
    for (int j = 0; j < 4; j++) {
        int e = base + j;
        if (e < N_EDGES) {
            if (is64) { s[j] = w[2 * e]; d[j] = w[2 * (N_EDGES + e)]; }
            else      { s[j] = w[e];     d[j] = w[N_EDGES + e]; }
        } else s[j] = -1;
    }
    #pragma unroll
    for (int j = 0; j < 4; j++)
        if (s[j] >= 0) { av[j] = g_asrc[s[j]]; bv[j] = g_adst[d[j]]; }
    #pragma unroll
    for (int j = 0; j < 4; j++)
        if (s[j] >= 0) slot[j] = atomicAdd(&g_count[d[j]], 1);
    #pragma unroll
    for (int j = 0; j < 4; j++) {
        if (s[j] >= 0 && slot[j] < MAXDEG) {
            float e = av[j] + bv[j];
            e = (e > 0.0f) ? e : NEG_SLOPE * e;
            float p = __expf(e);
            size_t o = (size_t)d[j] * MAXDEG + slot[j];
            g_slots[o] = s[j];
            g_pvals[o] = p;
            atomicAdd(&g_denom[d[j]], p);
        }
    }
}

// ---------------- K3: per-node aggregation (warp/node) ----------------------
// Coalesced 32-wide batch load of (src, p), shfl distribution, 4 subgroups of
// 8 lanes each handling one edge per step (8 cols x float4-pair per lane).
__global__ __launch_bounds__(256) void k_aggr(const float* __restrict__ bias,
                                              float* __restrict__ out) {
    int n = (blockIdx.x * blockDim.x + threadIdx.x) >> 5;
    if (n >= N_NODES) return;
    const int lane = threadIdx.x & 31;
    const int g8 = lane >> 3;
    const int qi = lane & 7;

    int deg = g_count[n];
    deg = deg < MAXDEG ? deg : MAXDEG;
    const int* slots = g_slots + (size_t)n * MAXDEG;
    const float* pvals = g_pvals + (size_t)n * MAXDEG;

    float4 a0 = make_float4(0.f, 0.f, 0.f, 0.f);
    float4 a1 = make_float4(0.f, 0.f, 0.f, 0.f);

    for (int base = 0; base < deg; base += 32) {
        int li = base + lane;
        int cl = li < deg ? li : (deg - 1);
        int sv = slots[cl];        // coalesced batch loads
        float pv = pvals[cl];
        int m = deg - base;
        #pragma unroll
        for (int j = 0; j < 32; j += 4) {
            if (j >= m) break;
            int idx = j + g8;
            int s = __shfl_sync(0xffffffffu, sv, idx);
            float p = __shfl_sync(0xffffffffu, pv, idx);
            if (idx < m) {
                const float4* hp = (const float4*)(g_h + (size_t)s * OUT_F);
                float4 h0 = hp[qi];
                float4 h1 = hp[8 + qi];
                a0.x = fmaf(p, h0.x, a0.x); a0.y = fmaf(p, h0.y, a0.y);
                a0.z = fmaf(p, h0.z, a0.z); a0.w = fmaf(p, h0.w, a0.w);
                a1.x = fmaf(p, h1.x, a1.x); a1.y = fmaf(p, h1.y, a1.y);
                a1.z = fmaf(p, h1.z, a1.z); a1.w = fmaf(p, h1.w, a1.w);
            }
        }
    }

    // reduce across the 4 subgroups
    #pragma unroll
    for (int o = 8; o <= 16; o <<= 1) {
        a0.x += __shfl_xor_sync(0xffffffffu, a0.x, o);
        a0.y += __shfl_xor_sync(0xffffffffu, a0.y, o);
        a0.z += __shfl_xor_sync(0xffffffffu, a0.z, o);
        a0.w += __shfl_xor_sync(0xffffffffu, a0.w, o);
        a1.x += __shfl_xor_sync(0xffffffffu, a1.x, o);
        a1.y += __shfl_xor_sync(0xffffffffu, a1.y, o);
        a1.z += __shfl_xor_sync(0xffffffffu, a1.z, o);
        a1.w += __shfl_xor_sync(0xffffffffu, a1.w, o);
    }

    if (lane < 8) {
        // self loop + epilogue
        float e = g_asrc[n] + g_adst[n];
        e = (e > 0.0f) ? e : NEG_SLOPE * e;
        float p = __expf(e);
        const float4* hp = (const float4*)(g_h + (size_t)n * OUT_F);
        float4 h0 = hp[qi], h1 = hp[8 + qi];
        a0.x = fmaf(p, h0.x, a0.x); a0.y = fmaf(p, h0.y, a0.y);
        a0.z = fmaf(p, h0.z, a0.z); a0.w = fmaf(p, h0.w, a0.w);
        a1.x = fmaf(p, h1.x, a1.x); a1.y = fmaf(p, h1.y, a1.y);
        a1.z = fmaf(p, h1.z, a1.z); a1.w = fmaf(p, h1.w, a1.w);

        float inv = 1.0f / (g_denom[n] + p + 1e-16f);
        float4 b0 = ((const float4*)bias)[qi];
        float4 b1 = ((const float4*)bias)[8 + qi];
        float4 o0, o1;
        o0.x = fmaf(a0.x, inv, b0.x); o0.y = fmaf(a0.y, inv, b0.y);
        o0.z = fmaf(a0.z, inv, b0.z); o0.w = fmaf(a0.w, inv, b0.w);
        o1.x = fmaf(a1.x, inv, b1.x); o1.y = fmaf(a1.y, inv, b1.y);
        o1.z = fmaf(a1.z, inv, b1.z); o1.w = fmaf(a1.w, inv, b1.w);
        o0.x = o0.x > 0.f ? o0.x : 0.f; o0.y = o0.y > 0.f ? o0.y : 0.f;
        o0.z = o0.z > 0.f ? o0.z : 0.f; o0.w = o0.w > 0.f ? o0.w : 0.f;
        o1.x = o1.x > 0.f ? o1.x : 0.f; o1.y = o1.y > 0.f ? o1.y : 0.f;
        o1.z = o1.z > 0.f ? o1.z : 0.f; o1.w = o1.w > 0.f ? o1.w : 0.f;
        ((float4*)out)[(size_t)n * 16 + qi]     = o0;
        ((float4*)out)[(size_t)n * 16 + 8 + qi] = o1;
    }
}

// ---------------- launch ----------------
extern "C" void kernel_launch(void* const* d_in, const int* in_sizes, int n_in,
                              void* d_out, int out_size) {
    const float* x       = (const float*)d_in[0];
    const void*  ei      = d_in[1];
    const float* W       = (const float*)d_in[2];
    const float* att_src = (const float*)d_in[3];
    const float* att_dst = (const float*)d_in[4];
    const float* bias    = (const float*)d_in[5];
    float* out = (float*)d_out;
    (void)in_sizes; (void)n_in; (void)out_size;

    k_detz<<<(N_NODES + 255) / 256, 256>>>((const unsigned int*)ei);
    k_gemm<<<(N_NODES + 31) / 32, 128>>>(x, W, att_src, att_dst);
    k_fill<<<(N_EDGES / 4 + 255) / 256, 256>>>(ei);
    k_aggr<<<((size_t)N_NODES * 32 + 255) / 256, 256>>>(bias, out);
}

// round 7
// speedup vs baseline: 1.1269x; 1.1269x over previous
#include <cuda_runtime.h>

#define N_NODES 50000
#define N_EDGES 800000
#define IN_F    128
#define OUT_F   64
#define NEG_SLOPE 0.2f
#define MAXDEG  128   // deg ~ Poisson(16); max over 50K nodes ~50. Huge margin.
#define RPB     128   // gemm rows per block

// ---------------- scratch (static device globals; no allocs) ----------------
__device__ float g_h[(size_t)N_NODES * OUT_F];          // 12.8 MB
__device__ float g_asrc[N_NODES];
__device__ float g_adst[N_NODES];
__device__ int   g_count[N_NODES];
__device__ int   g_slots[(size_t)N_NODES * MAXDEG];     // src ids, 25.6 MB
__device__ int   g_is64;

// ---------------- K0: zero counts + detect dtype (block 0) ------------------
// int64 LE: every odd 32-bit word is 0 (ids in [0,50000)). int32: odd words
// are node ids; 1024 consecutive zeros is ~impossible.
__global__ void k_detz(const unsigned int* __restrict__ w) {
    int t = blockIdx.x * blockDim.x + threadIdx.x;
    if (t < N_NODES) g_count[t] = 0;
    if (blockIdx.x == 0) {
        int nz = 0;
        #pragma unroll
        for (int j = 0; j < 4; j++)
            nz |= (w[2 * (threadIdx.x + 256 * j) + 1] != 0u) ? 1 : 0;
        int any = __syncthreads_or(nz);
        if (threadIdx.x == 0) g_is64 = any ? 0 : 1;
    }
}

// ---------------- K1: h = x @ W, 128 rows/block, packed f32x2 ----------------
// 256 threads. Thread = (cp = lane -> cols 2cp,2cp+1; warp -> 16 rows = 8
// packed row-pairs). Per k per warp: 1 LDS.64 (w) + 4 LDS.128 (x, broadcast)
// -> 16 FFMA2 (76% fma-slot fraction). Dynamic smem: 96 KB.
__global__ __launch_bounds__(256) void k_gemm(const float* __restrict__ x,
                                              const float* __restrict__ W,
                                              const float* __restrict__ att_src,
                                              const float* __restrict__ att_dst) {
    extern __shared__ __align__(16) float sm[];
    float (*xs)[RPB]  = (float (*)[RPB])sm;                 // [128][128] k-major
    float (*Ws)[OUT_F] = (float (*)[OUT_F])(sm + IN_F * RPB); // [128][64]
    float (*hs)[OUT_F] = (float (*)[OUT_F])sm;              // epilogue alias

    const int tx = threadIdx.x;
    const int lane = tx & 31;
    const int warp = tx >> 5;          // 0..7
    const int rbase = blockIdx.x * RPB;

    const float as0 = att_src[lane], as1 = att_src[32 + lane];
    const float ad0 = att_dst[lane], ad1 = att_dst[32 + lane];

    {   // load W: 2048 float4 / 256 threads
        const float4* W4 = (const float4*)W;
        float4* Ws4 = (float4*)&Ws[0][0];
        #pragma unroll
        for (int i = 0; i < 8; i++) Ws4[tx + 256 * i] = W4[tx + 256 * i];
    }
    {   // load x tile transposed: 2 threads per row, 16 float4 each
        const int row = tx >> 1;
        const int half = tx & 1;
        const int grow = rbase + row;
        const float4* x4 = (const float4*)x;
        #pragma unroll
        for (int j = 0; j < 16; j++) {
            int k4 = half * 16 + j;
            float4 v = (grow < N_NODES) ? x4[(size_t)grow * (IN_F / 4) + k4]
                                        : make_float4(0.f, 0.f, 0.f, 0.f);
            xs[4 * k4 + 0][row] = v.x;
            xs[4 * k4 + 1][row] = v.y;
            xs[4 * k4 + 2][row] = v.z;
            xs[4 * k4 + 3][row] = v.w;
        }
    }
    __syncthreads();

    const int cp = lane;               // cols 2cp, 2cp+1
    unsigned long long acc[8][2];
    #pragma unroll
    for (int j = 0; j < 8; j++) { acc[j][0] = 0ull; acc[j][1] = 0ull; }

    #pragma unroll 2
    for (int k = 0; k < IN_F; k++) {
        float2 wv = *(const float2*)&Ws[k][2 * cp];
        unsigned long long w20, w21;
        asm("mov.b64 %0, {%1, %1};" : "=l"(w20) : "r"(__float_as_uint(wv.x)));
        asm("mov.b64 %0, {%1, %1};" : "=l"(w21) : "r"(__float_as_uint(wv.y)));
        const ulonglong2* xr = (const ulonglong2*)&xs[k][warp * 16];
        ulonglong2 q0 = xr[0], q1 = xr[1], q2 = xr[2], q3 = xr[3]; // broadcast
        unsigned long long xp[8] = {q0.x, q0.y, q1.x, q1.y,
                                    q2.x, q2.y, q3.x, q3.y};
        #pragma unroll
        for (int j = 0; j < 8; j++) {
            asm("fma.rn.f32x2 %0, %1, %2, %3;"
                : "=l"(acc[j][0]) : "l"(xp[j]), "l"(w20), "l"(acc[j][0]));
            asm("fma.rn.f32x2 %0, %1, %2, %3;"
                : "=l"(acc[j][1]) : "l"(xp[j]), "l"(w21), "l"(acc[j][1]));
        }
    }
    __syncthreads();   // xs reads done before aliasing as hs

    #pragma unroll
    for (int j = 0; j < 8; j++) {
        int r0 = warp * 16 + 2 * j;
        float2 lo = make_float2(__uint_as_float((unsigned)acc[j][0]),
                                __uint_as_float((unsigned)acc[j][1]));
        float2 hi = make_float2(__uint_as_float((unsigned)(acc[j][0] >> 32)),
                                __uint_as_float((unsigned)(acc[j][1] >> 32)));
        *(float2*)&hs[r0][2 * cp]     = lo;
        *(float2*)&hs[r0 + 1][2 * cp] = hi;
    }
    __syncthreads();

    {   // coalesced copy hs -> g_h (2048 float4 / 256 threads)
        const float4* hs4 = (const float4*)&hs[0][0];
        float4* gh4 = (float4*)g_h;
        #pragma unroll
        for (int i = 0; i < 8; i++) {
            int idx = tx + 256 * i;
            int r = idx >> 4;
            if (rbase + r < N_NODES)
                gh4[(size_t)(rbase + r) * 16 + (idx & 15)] = hs4[idx];
        }
    }

    // fused attn: warp w reduces rows 16w..16w+15
    #pragma unroll
    for (int rr = 0; rr < 16; rr++) {
        int r = warp * 16 + rr;
        float h0 = hs[r][lane], h1 = hs[r][32 + lane];
        float s = h0 * as0 + h1 * as1;
        float d = h0 * ad0 + h1 * ad1;
        #pragma unroll
        for (int o = 16; o; o >>= 1) {
            s += __shfl_xor_sync(0xffffffffu, s, o);
            d += __shfl_xor_sync(0xffffffffu, d, o);
        }
        int gr = rbase + r;
        if (lane == 0 && gr < N_NODES) { g_asrc[gr] = s; g_adst[gr] = d; }
    }
}

// ---------------- K2: bucket edges by destination, 4 edges/thread -----------
__global__ __launch_bounds__(256) void k_fill(const void* __restrict__ ei) {
    int base = (blockIdx.x * blockDim.x + threadIdx.x) * 4;
    const int* w = (const int*)ei;
    const bool is64 = (g_is64 != 0);

    int s[4], d[4], slot[4];
    #pragma unroll
    for (int j = 0; j < 4; j++) {
        int e = base + j;
        if (e < N_EDGES) {
            if (is64) { s[j] = w[2 * e]; d[j] = w[2 * (N_EDGES + e)]; }
            else      { s[j] = w[e];     d[j] = w[N_EDGES + e]; }
        } else s[j] = -1;
    }
    #pragma unroll
    for (int j = 0; j < 4; j++)
        if (s[j] >= 0) slot[j] = atomicAdd(&g_count[d[j]], 1);
    #pragma unroll
    for (int j = 0; j < 4; j++)
        if (s[j] >= 0 && slot[j] < MAXDEG)
            g_slots[(size_t)d[j] * MAXDEG + slot[j]] = s[j];
}

// ---------------- K3: per-node aggregation (warp/node) ----------------------
// Batch phase (per 32 edges): coalesced slot load, each lane computes p for
// ITS edge once (exp amortized 1/edge, not 8/edge). Inner step: 2 shfl +
// 2 LDG.128 + 8 FMA, no predication (invalid lanes carry p=0).
__global__ __launch_bounds__(256) void k_aggr(const float* __restrict__ bias,
                                              float* __restrict__ out) {
    int n = (blockIdx.x * blockDim.x + threadIdx.x) >> 5;
    if (n >= N_NODES) return;
    const int lane = threadIdx.x & 31;
    const int g8 = lane >> 3;
    const int qi = lane & 7;

    int deg = g_count[n];
    deg = deg < MAXDEG ? deg : MAXDEG;
    const float adst_n = g_adst[n];
    const int* slots = g_slots + (size_t)n * MAXDEG;

    float4 a0 = make_float4(0.f, 0.f, 0.f, 0.f);
    float4 a1 = make_float4(0.f, 0.f, 0.f, 0.f);
    float denom = 0.0f;

    for (int base = 0; base < deg; base += 32) {
        int li = base + lane;
        bool valid = li < deg;
        int sv = slots[valid ? li : (deg - 1)];   // coalesced; clamp is safe
        float e = g_asrc[sv] + adst_n;
        e = (e > 0.0f) ? e : NEG_SLOPE * e;
        float p = valid ? __expf(e) : 0.0f;       // p=0 -> zero contribution
        denom += p;
        int m = deg - base;
        #pragma unroll
        for (int j = 0; j < 32; j += 4) {
            if (j >= m) break;
            int idx = j + g8;
            int s  = __shfl_sync(0xffffffffu, sv, idx);
            float pp = __shfl_sync(0xffffffffu, p, idx);
            const float4* hp =
                (const float4*)((const char*)g_h + ((unsigned)s << 8));
            float4 h0 = hp[qi];
            float4 h1 = hp[8 + qi];
            a0.x = fmaf(pp, h0.x, a0.x); a0.y = fmaf(pp, h0.y, a0.y);
            a0.z = fmaf(pp, h0.z, a0.z); a0.w = fmaf(pp, h0.w, a0.w);
            a1.x = fmaf(pp, h1.x, a1.x); a1.y = fmaf(pp, h1.y, a1.y);
            a1.z = fmaf(pp, h1.z, a1.z); a1.w = fmaf(pp, h1.w, a1.w);
        }
    }

    // reduce: acc across 4 subgroups; denom across whole warp
    denom += __shfl_xor_sync(0xffffffffu, denom, 1);
    denom += __shfl_xor_sync(0xffffffffu, denom, 2);
    denom += __shfl_xor_sync(0xffffffffu, denom, 4);
    #pragma unroll
    for (int o = 8; o <= 16; o <<= 1) {
        a0.x += __shfl_xor_sync(0xffffffffu, a0.x, o);
        a0.y += __shfl_xor_sync(0xffffffffu, a0.y, o);
        a0.z += __shfl_xor_sync(0xffffffffu, a0.z, o);
        a0.w += __shfl_xor_sync(0xffffffffu, a0.w, o);
        a1.x += __shfl_xor_sync(0xffffffffu, a1.x, o);
        a1.y += __shfl_xor_sync(0xffffffffu, a1.y, o);
        a1.z += __shfl_xor_sync(0xffffffffu, a1.z, o);
        a1.w += __shfl_xor_sync(0xffffffffu, a1.w, o);
        denom += __shfl_xor_sync(0xffffffffu, denom, o);
    }

    if (lane < 8) {
        // self loop + epilogue
        float e = g_asrc[n] + adst_n;
        e = (e > 0.0f) ? e : NEG_SLOPE * e;
        float p = __expf(e);
        const float4* hp =
            (const float4*)((const char*)g_h + ((unsigned)n << 8));
        float4 h0 = hp[qi], h1 = hp[8 + qi];
        a0.x = fmaf(p, h0.x, a0.x); a0.y = fmaf(p, h0.y, a0.y);
        a0.z = fmaf(p, h0.z, a0.z); a0.w = fmaf(p, h0.w, a0.w);
        a1.x = fmaf(p, h1.x, a1.x); a1.y = fmaf(p, h1.y, a1.y);
        a1.z = fmaf(p, h1.z, a1.z); a1.w = fmaf(p, h1.w, a1.w);

        float inv = 1.0f / (denom + p + 1e-16f);
        float4 b0 = ((const float4*)bias)[qi];
        float4 b1 = ((const float4*)bias)[8 + qi];
        float4 o0, o1;
        o0.x = fmaf(a0.x, inv, b0.x); o0.y = fmaf(a0.y, inv, b0.y);
        o0.z = fmaf(a0.z, inv, b0.z); o0.w = fmaf(a0.w, inv, b0.w);
        o1.x = fmaf(a1.x, inv, b1.x); o1.y = fmaf(a1.y, inv, b1.y);
        o1.z = fmaf(a1.z, inv, b1.z); o1.w = fmaf(a1.w, inv, b1.w);
        o0.x = o0.x > 0.f ? o0.x : 0.f; o0.y = o0.y > 0.f ? o0.y : 0.f;
        o0.z = o0.z > 0.f ? o0.z : 0.f; o0.w = o0.w > 0.f ? o0.w : 0.f;
        o1.x = o1.x > 0.f ? o1.x : 0.f; o1.y = o1.y > 0.f ? o1.y : 0.f;
        o1.z = o1.z > 0.f ? o1.z : 0.f; o1.w = o1.w > 0.f ? o1.w : 0.f;
        ((float4*)out)[(size_t)n * 16 + qi]     = o0;
        ((float4*)out)[(size_t)n * 16 + 8 + qi] = o1;
    }
}

// ---------------- launch ----------------
extern "C" void kernel_launch(void* const* d_in, const int* in_sizes, int n_in,
                              void* d_out, int out_size) {
    const float* x       = (const float*)d_in[0];
    const void*  ei      = d_in[1];
    const float* W       = (const float*)d_in[2];
    const float* att_src = (const float*)d_in[3];
    const float* att_dst = (const float*)d_in[4];
    const float* bias    = (const float*)d_in[5];
    float* out = (float*)d_out;
    (void)in_sizes; (void)n_in; (void)out_size;

    const int GEMM_SMEM = (IN_F * RPB + IN_F * OUT_F) * (int)sizeof(float); // 96 KB
    static int smem_set = 0;
    if (!smem_set) {
        cudaFuncSetAttribute(k_gemm, cudaFuncAttributeMaxDynamicSharedMemorySize,
                             GEMM_SMEM);
        smem_set = 1;
    }

    k_detz<<<(N_NODES + 255) / 256, 256>>>((const unsigned int*)ei);
    k_gemm<<<(N_NODES + RPB - 1) / RPB, 256, GEMM_SMEM>>>(x, W, att_src, att_dst);
    k_fill<<<(N_EDGES / 4 + 255) / 256, 256>>>(ei);
    k_aggr<<<((size_t)N_NODES * 32 + 255) / 256, 256>>>(bias, out);
}